// round 12
// baseline (speedup 1.0000x reference)
#include <cuda_runtime.h>
#include <cfloat>
#include <cstdint>

#define BB 8
#define CC 3
#define HH 1080
#define WW 1920
#define KK 256
#define NBASIS 25
#define GBINS 2048              // bins centered at g/2048, width 1/2048 (magic-RN)
#define NBINS 2049              // g in [0, 2048]
#define NBINS_PAD 2050          // pad to float4 multiple (2050*8B = 16.4KB)
#define NSEG (KK + 1)           // 257 extended segments
#define PIX_PER_BATCH (CC * HH * WW)   // 6,220,800
#define NF4 (PIX_PER_BATCH / 4)        // 1,555,200
#define GX 148                          // blocks per batch: 148*8 = 1184 CTAs
#define STRIDE (GX * 256)               // 37,888
#define MAGIC 8388608.0f                // 2^23

// Bin entry (float2), bin g covers [(2g-1)/4096, (2g+1)/4096):
//   pure bin -> (slope a, intercept b) of containing segment; y = a*x+b EXACT
//   kinked   -> a = fp32 NaN with payload 0x7FC00000|(k0+1), b unused
__device__ float2 gBins[BB * NBINS_PAD];
__device__ float  gSegHi[BB * NSEG];   // segment upper bound E[k] (FLT_MAX for k=K)
__device__ float2 gSegAB[BB * NSEG];   // exact (slope, intercept)

// ---------------------------------------------------------------------------
// Table builder: grid (BB, 9), 256 threads.
//   parts 0..8 build bins g = part*256+t (g <= 2048); part 8 also builds the
//   segment table and pads entry 2049.
// ---------------------------------------------------------------------------
__global__ void tmo_tables(const float* __restrict__ w,
                           const float* __restrict__ E,
                           const float* __restrict__ f0,
                           const float* __restrict__ Hb) {
    __shared__ float sE[KK];
    __shared__ float sC[KK];
    const int b = blockIdx.x;
    const int part = blockIdx.y;
    const int t = threadIdx.x;

    {
        float acc = f0[t];
        #pragma unroll
        for (int n = 0; n < NBASIS; n++)
            acc = fmaf(Hb[t * NBASIS + n], w[b * NBASIS + n], acc);
        sE[t] = E[t];
        sC[t] = acc;
    }
    __syncthreads();

    if (part == 8) {
        for (int k = t; k < NSEG; k += blockDim.x) {
            float hi; float2 ab;
            if (k == 0) {
                hi = sE[0];            ab = make_float2(0.0f, sC[0]);
            } else if (k == KK) {
                hi = FLT_MAX;          ab = make_float2(0.0f, sC[KK - 1]);
            } else {
                float a = (sC[k] - sC[k - 1]) / (sE[k] - sE[k - 1]);
                hi = sE[k];            ab = make_float2(a, fmaf(-a, sE[k - 1], sC[k - 1]));
            }
            gSegHi[b * NSEG + k] = hi;
            gSegAB[b * NSEG + k] = ab;
        }
        if (t == 0)   // padding entry
            gBins[b * NBINS_PAD + 2049] = make_float2(0.0f, 0.0f);
    }

    const int g = part * 256 + t;
    if (g < NBINS) {
        // Bin boundaries for round-to-nearest indexing (exact: odd * 2^-12)
        float left  = (float)(2 * g - 1) * (1.0f / 4096.0f);
        float right = (float)(2 * g + 1) * (1.0f / 4096.0f);
        int lo = 0, hi = KK;
        while (lo < hi) {                // k0 = #E <= left
            int mid = (lo + hi) >> 1;
            if (sE[mid] <= left) lo = mid + 1; else hi = mid;
        }
        int k0 = lo;
        float upper = (k0 < KK) ? sE[k0] : FLT_MAX;
        float2 ab;
        if (upper >= right) {
            // entire bin inside extended segment k0: exact (a, b)
            if (k0 == 0) {
                ab = make_float2(0.0f, sC[0]);
            } else if (k0 == KK) {
                ab = make_float2(0.0f, sC[KK - 1]);
            } else {
                float a = (sC[k0] - sC[k0 - 1]) / (sE[k0] - sE[k0 - 1]);
                ab = make_float2(a, fmaf(-a, sE[k0 - 1], sC[k0 - 1]));
            }
        } else {
            ab = make_float2(__int_as_float(0x7FC00000 | (uint32_t)(k0 + 1)), 0.0f);
        }
        gBins[b * NBINS_PAD + g] = ab;
    }
}

// ---------------------------------------------------------------------------
// Fast path: magic-number bin index (no CVT ops), one LDS.64, one FFMA —
// exact. NaN result (~12% of lanes) triggers exact fp32 segment walk.
// ---------------------------------------------------------------------------
__device__ __forceinline__ float tmo_eval(float x, const float2* sBins,
                                          const float* sHi, const float2* sAB) {
    float s = fmaf(x, 2048.0f, MAGIC);          // RN -> integer g in mantissa
    int g = __float_as_int(s) & 0x0FFF;         // g in [0, 2048]
    float2 ab = sBins[g];
    float y = fmaf(ab.x, x, ab.y);
    if (!(y == y)) {                            // NaN => kinked bin
        int k = (__float_as_int(ab.x) & 0x3FF) - 1;
        while (x >= sHi[k]) k++;
        float2 st = sAB[k];
        y = fmaf(st.x, x, st.y);
    }
    return __saturatef(y);
}

// ---------------------------------------------------------------------------
// Main kernel: grid (148, 8) = 1184 blocks = one uniform wave at 8 CTAs/SM
// (~19.5 KB smem, 32-reg cap). Software pipeline: next LDG.128 in flight.
// ---------------------------------------------------------------------------
__global__ void __launch_bounds__(256, 8)
tmo_apply(const float* __restrict__ img, float* __restrict__ out) {
    __shared__ float2 sBins[NBINS_PAD];   // 16.4 KB
    __shared__ float  sHi[NSEG];          // ~1 KB
    __shared__ float2 sAB[NSEG];          // ~2 KB

    const int b = blockIdx.y;

    {
        const float4* src = reinterpret_cast<const float4*>(gBins + (size_t)b * NBINS_PAD);
        float4* dst = reinterpret_cast<float4*>(sBins);
        for (int i = threadIdx.x; i < NBINS_PAD / 2; i += blockDim.x) dst[i] = src[i];
        for (int i = threadIdx.x; i < NSEG; i += blockDim.x) {
            sHi[i] = gSegHi[b * NSEG + i];
            sAB[i] = gSegAB[b * NSEG + i];
        }
    }
    __syncthreads();

    const float4* in4  = reinterpret_cast<const float4*>(img + (size_t)b * PIX_PER_BATCH);
    float4*       out4 = reinterpret_cast<float4*>(out + (size_t)b * PIX_PER_BATCH);

    int i = blockIdx.x * blockDim.x + threadIdx.x;   // < STRIDE <= NF4, so >=1 elem

    float4 v = in4[i];
    int nxt = i + STRIDE;

    #pragma unroll 1
    while (nxt < NF4) {
        float4 vn = in4[nxt];            // prefetch: overlaps with processing below
        float4 r;
        r.x = tmo_eval(v.x, sBins, sHi, sAB);
        r.y = tmo_eval(v.y, sBins, sHi, sAB);
        r.z = tmo_eval(v.z, sBins, sHi, sAB);
        r.w = tmo_eval(v.w, sBins, sHi, sAB);
        out4[i] = r;
        v = vn;
        i = nxt;
        nxt += STRIDE;
    }
    {
        float4 r;
        r.x = tmo_eval(v.x, sBins, sHi, sAB);
        r.y = tmo_eval(v.y, sBins, sHi, sAB);
        r.z = tmo_eval(v.z, sBins, sHi, sAB);
        r.w = tmo_eval(v.w, sBins, sHi, sAB);
        out4[i] = r;
    }
}

extern "C" void kernel_launch(void* const* d_in, const int* in_sizes, int n_in,
                              void* d_out, int out_size) {
    const float* hdr = (const float*)d_in[0];   // [B,C,H,W]
    const float* w   = (const float*)d_in[1];   // [B,NB]
    const float* E   = (const float*)d_in[2];   // [K]
    const float* f0  = (const float*)d_in[3];   // [K]
    const float* Hb  = (const float*)d_in[4];   // [K,NB]
    float* out = (float*)d_out;

    tmo_tables<<<dim3(BB, 9), 256>>>(w, E, f0, Hb);

    dim3 grid(GX, BB);   // 1184 blocks = single uniform wave at 8 CTAs/SM
    tmo_apply<<<grid, 256>>>(hdr, out);
}